// round 7
// baseline (speedup 1.0000x reference)
#include <cuda_runtime.h>
#include <cuda_fp16.h>
#include <cstdint>

typedef unsigned long long u64;
typedef uint32_t u32;

#define NB 4096
#define NE 16
#define ND 512
#define NH 2048

#define KC 64                          // k-chunk: 64 fp16 = 128B rows
#define XTILE 16384                    // 128 x 64 fp16
#define WTILE 8192                     // 64 x 64 fp16
#define STAGE (XTILE + WTILE)          // 24576
#define NSTAGE 4
#define OFF_STAGES 4096                // after d-table (16*64 floats)
#define SMEM_TOTAL (OFF_STAGES + NSTAGE * STAGE)   // 102400 B -> occupancy 2

// ---------------- scratch (device globals; no allocations allowed) ----------
__device__ __half g_xh[NB * ND];
__device__ __half g_wh[NE * NH * ND];
__device__ float  g_dcomb[NE * NH];

// ---------------- PTX helpers ----------------------------------------------
__device__ __forceinline__ u32 smem_u32(const void* p) {
    u32 a;
    asm("{ .reg .u64 t; cvta.to.shared.u64 t, %1; cvt.u32.u64 %0, t; }" : "=r"(a) : "l"(p));
    return a;
}
__device__ __forceinline__ void cp16(u32 dst, const void* src) {
    asm volatile("cp.async.cg.shared.global [%0], [%1], 16;" :: "r"(dst), "l"(src) : "memory");
}
__device__ __forceinline__ void cp_commit() { asm volatile("cp.async.commit_group;" ::: "memory"); }
__device__ __forceinline__ void cp_wait2()  { asm volatile("cp.async.wait_group 2;" ::: "memory"); }

__device__ __forceinline__ void ldsm4(u32& r0, u32& r1, u32& r2, u32& r3, u32 addr) {
    asm volatile("ldmatrix.sync.aligned.m8n8.x4.shared.b16 {%0,%1,%2,%3}, [%4];"
                 : "=r"(r0), "=r"(r1), "=r"(r2), "=r"(r3) : "r"(addr));
}
__device__ __forceinline__ void mma16816(float* c, const u32* a, const u32* b) {
    asm volatile("mma.sync.aligned.m16n8k16.row.col.f32.f16.f16.f32 "
                 "{%0,%1,%2,%3}, {%4,%5,%6,%7}, {%8,%9}, {%0,%1,%2,%3};"
                 : "+f"(c[0]), "+f"(c[1]), "+f"(c[2]), "+f"(c[3])
                 : "r"(a[0]), "r"(a[1]), "r"(a[2]), "r"(a[3]), "r"(b[0]), "r"(b[1]));
}

__device__ __forceinline__ u32 swz128(u32 off) { return off ^ ((off >> 3) & 0x70); }

// ---------------- fused prep kernel ------------------------------------------
// blocks [0, 4096): W rows -> fp16 + d = bias - c_e.W_row  (1 warp per row)
// blocks [4096, 6144): x -> fp16
__global__ void prep_kernel(const float* __restrict__ x,
                            const float* __restrict__ W,
                            const float* __restrict__ centers,
                            const float* __restrict__ bias) {
    int b = blockIdx.x;
    if (b < 4096) {
        int gw   = b * 8 + (threadIdx.x >> 5);
        int lane = threadIdx.x & 31;
        int e = gw >> 11;
        const float4* wr = (const float4*)(W + (size_t)gw * ND);
        const float4* cr = (const float4*)(centers + (size_t)e * ND);
        __half2* ph = (__half2*)(g_wh + (size_t)gw * ND);
        float s = 0.f;
#pragma unroll
        for (int i = 0; i < ND / 128; i++) {
            int idx = lane + 32 * i;
            float4 w4 = wr[idx];
            float4 c4 = cr[idx];
            s += w4.x * c4.x + w4.y * c4.y + w4.z * c4.z + w4.w * c4.w;
            ph[2 * idx]     = __half2(__float2half_rn(w4.x), __float2half_rn(w4.y));
            ph[2 * idx + 1] = __half2(__float2half_rn(w4.z), __float2half_rn(w4.w));
        }
#pragma unroll
        for (int o = 16; o; o >>= 1) s += __shfl_xor_sync(0xffffffffu, s, o);
        if (lane == 0) g_dcomb[gw] = bias[gw] - s;
    } else {
        int i = (b - 4096) * 256 + threadIdx.x;
        float4 v = ((const float4*)x)[i];
        __half2* ph = (__half2*)g_xh;
        ph[2 * i]     = __half2(__float2half_rn(v.x), __float2half_rn(v.y));
        ph[2 * i + 1] = __half2(__float2half_rn(v.z), __float2half_rn(v.w));
    }
}

// ---------------- main GEMM kernel -------------------------------------------
// grid (NH/64, NB/128) = (32, 32) = 1024 CTAs; 256 threads, occupancy 2.
// 8 warps: wm = (wid&3)*32 (4 m-warps), wn = (wid>>2)*32 (2 n-warps);
// warp tile 32x32. 128 chunks = 16 experts x 8 k-chunks of 64.

__device__ __forceinline__ void load_chunk(int gc, u32 dst, int mb, int hb, int tid) {
    int e = gc >> 3, kc = (gc & 7) * KC;
    // X tile 128x64: 1024 cp16 -> 4/thread. row = tid>>1, half = tid&1.
    int xrow = tid >> 1, xh2 = tid & 1;
    const __half* px = g_xh + (size_t)(mb + xrow) * ND + kc + xh2 * 8;
#pragma unroll
    for (int i = 0; i < 4; i++) {
        u32 so = swz128((u32)(xrow * 128 + xh2 * 16 + i * 32));
        cp16(dst + so, px + i * 16);
    }
    // W tile 64x64: 512 cp16 -> 2/thread. row = tid>>2, q = tid&3.
    int wrow = tid >> 2, wq = tid & 3;
    const __half* pw = g_wh + (size_t)(e * NH + hb + wrow) * ND + kc + wq * 8;
#pragma unroll
    for (int i = 0; i < 2; i++) {
        u32 so = swz128((u32)(wrow * 128 + wq * 16 + i * 64));
        cp16(dst + XTILE + so, pw + i * 32);
    }
}

__global__ void __launch_bounds__(256, 2)
gemm_kernel(float* __restrict__ out) {
    extern __shared__ char smem[];
    float* dsm = (float*)smem;                     // [16][64] combined bias
    u32 sb = smem_u32(smem) + OFF_STAGES;
    const int tid = threadIdx.x, wid = tid >> 5, lane = tid & 31;
    const int hb = blockIdx.x * 64, mb = blockIdx.y * 128;
    const int wm = (wid & 3) * 32, wn = (wid >> 2) * 32;

    // stage the per-expert combined bias slice for this CTA
#pragma unroll
    for (int i = tid; i < NE * 64; i += 256)
        dsm[i] = g_dcomb[(size_t)(i >> 6) * NH + hb + (i & 63)];

    load_chunk(0, sb + 0 * STAGE, mb, hb, tid); cp_commit();
    load_chunk(1, sb + 1 * STAGE, mb, hb, tid); cp_commit();
    load_chunk(2, sb + 2 * STAGE, mb, hb, tid); cp_commit();

    float acc[2][4][4], oacc[2][4][4];
#pragma unroll
    for (int a = 0; a < 2; a++)
#pragma unroll
        for (int b = 0; b < 4; b++)
#pragma unroll
            for (int c = 0; c < 4; c++) { acc[a][b][c] = 0.f; oacc[a][b][c] = 0.f; }

    for (int gc = 0; gc < 128; gc++) {
        cp_wait2();
        __syncthreads();

        // issue next prefetch FIRST so cp.async overlaps with this chunk's math
        if (gc + 3 < 128) load_chunk(gc + 3, sb + (u32)((gc + 3) & 3) * STAGE, mb, hb, tid);
        cp_commit();

        u32 st = sb + (u32)(gc & 3) * STAGE;
        u32 Ah = st, Bh = st + XTILE;

#pragma unroll
        for (int ks = 0; ks < 4; ks++) {
            u32 ah[2][4], bh[4][2];
            u32 arel = swz128((u32)((lane & 15) * 128 + ks * 32 + (lane >> 4) * 16));
#pragma unroll
            for (int mt = 0; mt < 2; mt++) {
                u32 ao = (u32)((wm + mt * 16) * 128) + arel;
                ldsm4(ah[mt][0], ah[mt][1], ah[mt][2], ah[mt][3], Ah + ao);
            }
            u32 brel = swz128((u32)((lane & 7) * 128 + ks * 32 + ((lane >> 3) & 1) * 16));
#pragma unroll
            for (int pr = 0; pr < 2; pr++) {
                u32 bo = (u32)((wn + pr * 16 + ((lane >> 4) & 1) * 8) * 128) + brel;
                ldsm4(bh[pr * 2][0], bh[pr * 2][1], bh[pr * 2 + 1][0], bh[pr * 2 + 1][1], Bh + bo);
            }
#pragma unroll
            for (int mt = 0; mt < 2; mt++)
#pragma unroll
                for (int nt = 0; nt < 4; nt++)
                    mma16816(acc[mt][nt], ah[mt], bh[nt]);
        }

        if ((gc & 7) == 7) {    // finished expert e: relu + accumulate, reset
            int e = gc >> 3;
            const float2* dp = (const float2*)(dsm + e * 64 + wn);
#pragma unroll
            for (int nt = 0; nt < 4; nt++) {
                float2 d2 = dp[nt * 4 + (lane & 3)];
#pragma unroll
                for (int mt = 0; mt < 2; mt++) {
                    oacc[mt][nt][0] += fmaxf(acc[mt][nt][0] + d2.x, 0.f);
                    oacc[mt][nt][1] += fmaxf(acc[mt][nt][1] + d2.y, 0.f);
                    oacc[mt][nt][2] += fmaxf(acc[mt][nt][2] + d2.x, 0.f);
                    oacc[mt][nt][3] += fmaxf(acc[mt][nt][3] + d2.y, 0.f);
                    acc[mt][nt][0] = 0.f; acc[mt][nt][1] = 0.f;
                    acc[mt][nt][2] = 0.f; acc[mt][nt][3] = 0.f;
                }
            }
        }
    }

    // store: C fragment mapping — (row t/4 [+8], col 2*(t%4) [+1])
#pragma unroll
    for (int mt = 0; mt < 2; mt++)
#pragma unroll
        for (int nt = 0; nt < 4; nt++) {
            int r0 = mb + wm + mt * 16 + (lane >> 2);
            int cc = hb + wn + nt * 8 + 2 * (lane & 3);
            *(float2*)(out + (size_t)r0 * NH + cc) =
                make_float2(oacc[mt][nt][0], oacc[mt][nt][1]);
            *(float2*)(out + (size_t)(r0 + 8) * NH + cc) =
                make_float2(oacc[mt][nt][2], oacc[mt][nt][3]);
        }
}

// ---------------- launch -----------------------------------------------------
extern "C" void kernel_launch(void* const* d_in, const int* in_sizes, int n_in,
                              void* d_out, int out_size) {
    const float* x       = (const float*)d_in[0];  // [B, D]
    const float* centers = (const float*)d_in[1];  // [E, D]
    const float* W       = (const float*)d_in[2];  // [E, H, D]
    const float* bias    = (const float*)d_in[3];  // [E, H]
    float* out = (float*)d_out;                    // [B, H]

    cudaFuncSetAttribute(gemm_kernel, cudaFuncAttributeMaxDynamicSharedMemorySize, SMEM_TOTAL);

    prep_kernel<<<4096 + 2048, 256>>>(x, W, centers, bias);

    dim3 grid(NH / 64, NB / 128);    // (32, 32) = 1024 CTAs
    gemm_kernel<<<grid, 256, SMEM_TOTAL>>>(out);
}

// round 8
// speedup vs baseline: 1.2363x; 1.2363x over previous
#include <cuda_runtime.h>
#include <cuda_fp16.h>
#include <cstdint>

typedef unsigned long long u64;
typedef uint32_t u32;

#define NB 4096
#define NE 16
#define ND 512
#define NH 2048

#define KC 64                          // k-chunk: 64 fp16 = 128B rows
#define TILE 16384                     // 128 x 64 fp16 tile bytes
#define STAGE (2 * TILE)               // xh, wh
#define NSTAGE 5
#define OFF_STAGES 8192                // after d-table (16*128 floats)
#define SMEM_TOTAL (OFF_STAGES + NSTAGE * STAGE)   // 172032 B

// ---------------- scratch (device globals; no allocations allowed) ----------
__device__ __half g_xh[NB * ND];
__device__ __half g_wh[NE * NH * ND];
__device__ float  g_dcomb[NE * NH];

// ---------------- PTX helpers ----------------------------------------------
__device__ __forceinline__ u32 smem_u32(const void* p) {
    u32 a;
    asm("{ .reg .u64 t; cvta.to.shared.u64 t, %1; cvt.u32.u64 %0, t; }" : "=r"(a) : "l"(p));
    return a;
}
__device__ __forceinline__ void cp16(u32 dst, const void* src) {
    asm volatile("cp.async.cg.shared.global [%0], [%1], 16;" :: "r"(dst), "l"(src) : "memory");
}
__device__ __forceinline__ void cp_commit() { asm volatile("cp.async.commit_group;" ::: "memory"); }
__device__ __forceinline__ void cp_wait3()  { asm volatile("cp.async.wait_group 3;" ::: "memory"); }

__device__ __forceinline__ void ldsm4(u32& r0, u32& r1, u32& r2, u32& r3, u32 addr) {
    asm volatile("ldmatrix.sync.aligned.m8n8.x4.shared.b16 {%0,%1,%2,%3}, [%4];"
                 : "=r"(r0), "=r"(r1), "=r"(r2), "=r"(r3) : "r"(addr));
}
__device__ __forceinline__ void mma16816(float* c, const u32* a, const u32* b) {
    asm volatile("mma.sync.aligned.m16n8k16.row.col.f32.f16.f16.f32 "
                 "{%0,%1,%2,%3}, {%4,%5,%6,%7}, {%8,%9}, {%0,%1,%2,%3};"
                 : "+f"(c[0]), "+f"(c[1]), "+f"(c[2]), "+f"(c[3])
                 : "r"(a[0]), "r"(a[1]), "r"(a[2]), "r"(a[3]), "r"(b[0]), "r"(b[1]));
}

__device__ __forceinline__ u32 swz128(u32 off) { return off ^ ((off >> 3) & 0x70); }

// ---------------- fused prep kernel ------------------------------------------
// blocks [0, 4096): W rows -> fp16 + d = bias - c_e.W_row  (1 warp per row)
// blocks [4096, 6144): x -> fp16
__global__ void prep_kernel(const float* __restrict__ x,
                            const float* __restrict__ W,
                            const float* __restrict__ centers,
                            const float* __restrict__ bias) {
    int b = blockIdx.x;
    if (b < 4096) {
        int gw   = b * 8 + (threadIdx.x >> 5);
        int lane = threadIdx.x & 31;
        int e = gw >> 11;
        const float4* wr = (const float4*)(W + (size_t)gw * ND);
        const float4* cr = (const float4*)(centers + (size_t)e * ND);
        __half2* ph = (__half2*)(g_wh + (size_t)gw * ND);
        float s = 0.f;
#pragma unroll
        for (int i = 0; i < ND / 128; i++) {
            int idx = lane + 32 * i;
            float4 w4 = wr[idx];
            float4 c4 = cr[idx];
            s += w4.x * c4.x + w4.y * c4.y + w4.z * c4.z + w4.w * c4.w;
            ph[2 * idx]     = __half2(__float2half_rn(w4.x), __float2half_rn(w4.y));
            ph[2 * idx + 1] = __half2(__float2half_rn(w4.z), __float2half_rn(w4.w));
        }
#pragma unroll
        for (int o = 16; o; o >>= 1) s += __shfl_xor_sync(0xffffffffu, s, o);
        if (lane == 0) g_dcomb[gw] = bias[gw] - s;
    } else {
        int i = (b - 4096) * 256 + threadIdx.x;
        float4 v = ((const float4*)x)[i];
        __half2* ph = (__half2*)g_xh;
        ph[2 * i]     = __half2(__float2half_rn(v.x), __float2half_rn(v.y));
        ph[2 * i + 1] = __half2(__float2half_rn(v.z), __float2half_rn(v.w));
    }
}

// ---------------- main GEMM kernel -------------------------------------------
// grid (NH/128, NB/128) = (16, 32); 256 threads, 8 warps (2m x 4n of 64x32).
// 128 chunks = 16 experts x 8 k-chunks of 64. One fp16 MMA per (k16, mt, nt).
// Register-level fragment double buffering hides LDSM latency under MMAs.

__device__ __forceinline__ void load_chunk(int gc, u32 dst, int mb, int hb, int tid) {
    int e = gc >> 3, kc = (gc & 7) * KC;
    int row = tid >> 3, c = tid & 7;
    u32 so = swz128((u32)(row * 128 + c * 16));
    const __half* pxh = g_xh + (size_t)(mb + row) * ND + kc + c * 8;
    const __half* pwh = g_wh + (size_t)(e * NH + hb + row) * ND + kc + c * 8;
#pragma unroll
    for (int i = 0; i < 4; i++) {
        u32 d = dst + so + (u32)i * 4096;          // +32 rows per step
        size_t eo = (size_t)(32 * i) * ND;
        cp16(d + 0 * TILE, pxh + eo);
        cp16(d + 1 * TILE, pwh + eo);
    }
}

__device__ __forceinline__ void load_frags(int ks, u32 Ah, u32 Bh, int wm, int wn,
                                           int lane, u32 ah[4][4], u32 bh[4][2]) {
    u32 arel = swz128((u32)((lane & 15) * 128 + ks * 32 + (lane >> 4) * 16));
#pragma unroll
    for (int mt = 0; mt < 4; mt++) {
        u32 ao = (u32)((wm + mt * 16) * 128) + arel;
        ldsm4(ah[mt][0], ah[mt][1], ah[mt][2], ah[mt][3], Ah + ao);
    }
    u32 brel = swz128((u32)((lane & 7) * 128 + ks * 32 + ((lane >> 3) & 1) * 16));
#pragma unroll
    for (int pr = 0; pr < 2; pr++) {
        u32 bo = (u32)((wn + pr * 16 + ((lane >> 4) & 1) * 8) * 128) + brel;
        ldsm4(bh[pr * 2][0], bh[pr * 2][1], bh[pr * 2 + 1][0], bh[pr * 2 + 1][1], Bh + bo);
    }
}

__global__ void __launch_bounds__(256, 1)
gemm_kernel(float* __restrict__ out) {
    extern __shared__ char smem[];
    float* dsm = (float*)smem;                     // [16][128] combined bias
    u32 sb = smem_u32(smem) + OFF_STAGES;
    const int tid = threadIdx.x, wid = tid >> 5, lane = tid & 31;
    const int hb = blockIdx.x * 128, mb = blockIdx.y * 128;
    const int wm = (wid >> 2) * 64, wn = (wid & 3) * 32;

    // stage the per-expert combined bias slice for this CTA
#pragma unroll
    for (int i = tid; i < NE * 128; i += 256)
        dsm[i] = g_dcomb[(size_t)(i >> 7) * NH + hb + (i & 127)];

    load_chunk(0, sb + 0 * STAGE, mb, hb, tid); cp_commit();
    load_chunk(1, sb + 1 * STAGE, mb, hb, tid); cp_commit();
    load_chunk(2, sb + 2 * STAGE, mb, hb, tid); cp_commit();
    load_chunk(3, sb + 3 * STAGE, mb, hb, tid); cp_commit();

    float acc[4][4][4], oacc[4][4][4];
#pragma unroll
    for (int a = 0; a < 4; a++)
#pragma unroll
        for (int b = 0; b < 4; b++)
#pragma unroll
            for (int c = 0; c < 4; c++) { acc[a][b][c] = 0.f; oacc[a][b][c] = 0.f; }

    int st_idx = 0, pf_idx = 4;
    for (int gc = 0; gc < 128; gc++) {
        cp_wait3();
        __syncthreads();

        u32 st = sb + (u32)st_idx * STAGE;
        st_idx = (st_idx == NSTAGE - 1) ? 0 : st_idx + 1;
        u32 Ah = st, Bh = st + TILE;

        // fragment double buffer: kick off ks=0 loads immediately after the barrier
        u32 ah[2][4][4], bh[2][4][2];
        load_frags(0, Ah, Bh, wm, wn, lane, ah[0], bh[0]);

        // then issue the global->smem prefetch for chunk gc+4
        if (gc + 4 < 128) load_chunk(gc + 4, sb + (u32)pf_idx * STAGE, mb, hb, tid);
        cp_commit();
        pf_idx = (pf_idx == NSTAGE - 1) ? 0 : pf_idx + 1;

#pragma unroll
        for (int ks = 0; ks < 4; ks++) {
            int cb = ks & 1;
            if (ks < 3)
                load_frags(ks + 1, Ah, Bh, wm, wn, lane, ah[cb ^ 1], bh[cb ^ 1]);
#pragma unroll
            for (int mt = 0; mt < 4; mt++)
#pragma unroll
                for (int nt = 0; nt < 4; nt++)
                    mma16816(acc[mt][nt], ah[cb][mt], bh[cb][nt]);
        }

        if ((gc & 7) == 7) {    // finished expert e: relu + accumulate, reset
            int e = gc >> 3;
            const float2* dp = (const float2*)(dsm + e * 128 + wn);
#pragma unroll
            for (int nt = 0; nt < 4; nt++) {
                float2 d2 = dp[nt * 4 + (lane & 3)];
#pragma unroll
                for (int mt = 0; mt < 4; mt++) {
                    oacc[mt][nt][0] += fmaxf(acc[mt][nt][0] + d2.x, 0.f);
                    oacc[mt][nt][1] += fmaxf(acc[mt][nt][1] + d2.y, 0.f);
                    oacc[mt][nt][2] += fmaxf(acc[mt][nt][2] + d2.x, 0.f);
                    oacc[mt][nt][3] += fmaxf(acc[mt][nt][3] + d2.y, 0.f);
                    acc[mt][nt][0] = 0.f; acc[mt][nt][1] = 0.f;
                    acc[mt][nt][2] = 0.f; acc[mt][nt][3] = 0.f;
                }
            }
        }
    }

    // store: C fragment mapping — (row t/4 [+8], col 2*(t%4) [+1])
#pragma unroll
    for (int mt = 0; mt < 4; mt++)
#pragma unroll
        for (int nt = 0; nt < 4; nt++) {
            int r0 = mb + wm + mt * 16 + (lane >> 2);
            int cc = hb + wn + nt * 8 + 2 * (lane & 3);
            *(float2*)(out + (size_t)r0 * NH + cc) =
                make_float2(oacc[mt][nt][0], oacc[mt][nt][1]);
            *(float2*)(out + (size_t)(r0 + 8) * NH + cc) =
                make_float2(oacc[mt][nt][2], oacc[mt][nt][3]);
        }
}

// ---------------- launch -----------------------------------------------------
extern "C" void kernel_launch(void* const* d_in, const int* in_sizes, int n_in,
                              void* d_out, int out_size) {
    const float* x       = (const float*)d_in[0];  // [B, D]
    const float* centers = (const float*)d_in[1];  // [E, D]
    const float* W       = (const float*)d_in[2];  // [E, H, D]
    const float* bias    = (const float*)d_in[3];  // [E, H]
    float* out = (float*)d_out;                    // [B, H]

    cudaFuncSetAttribute(gemm_kernel, cudaFuncAttributeMaxDynamicSharedMemorySize, SMEM_TOTAL);

    prep_kernel<<<4096 + 2048, 256>>>(x, W, centers, bias);

    dim3 grid(NH / 128, NB / 128);   // (16, 32)
    gemm_kernel<<<grid, 256, SMEM_TOTAL>>>(out);
}

// round 9
// speedup vs baseline: 1.3321x; 1.0775x over previous
#include <cuda_runtime.h>
#include <cuda_fp16.h>
#include <cstdint>

typedef unsigned long long u64;
typedef uint32_t u32;

#define NB 4096
#define NE 16
#define ND 512
#define NH 2048

#define KC 64                          // k-chunk: 64 fp16 = 128B rows
#define TILE 16384                     // 128 x 64 fp16 tile bytes
#define STAGE (2 * TILE)               // x tile + w tile per chunk
#define NSTAGE 6
#define OFF_STAGES 8192                // after d-table (16*128 floats)
#define SMEM_TOTAL (OFF_STAGES + NSTAGE * STAGE)   // 204800 B

// ---------------- scratch (device globals; no allocations allowed) ----------
__device__ __half g_xh[NB * ND];
__device__ __half g_wh[NE * NH * ND];
__device__ float  g_dcomb[NE * NH];

// ---------------- PTX helpers ----------------------------------------------
__device__ __forceinline__ u32 smem_u32(const void* p) {
    u32 a;
    asm("{ .reg .u64 t; cvta.to.shared.u64 t, %1; cvt.u32.u64 %0, t; }" : "=r"(a) : "l"(p));
    return a;
}
__device__ __forceinline__ void cp16(u32 dst, const void* src) {
    asm volatile("cp.async.cg.shared.global [%0], [%1], 16;" :: "r"(dst), "l"(src) : "memory");
}
__device__ __forceinline__ void cp_commit() { asm volatile("cp.async.commit_group;" ::: "memory"); }
__device__ __forceinline__ void cp_wait1()  { asm volatile("cp.async.wait_group 1;" ::: "memory"); }

__device__ __forceinline__ void ldsm4(u32& r0, u32& r1, u32& r2, u32& r3, u32 addr) {
    asm volatile("ldmatrix.sync.aligned.m8n8.x4.shared.b16 {%0,%1,%2,%3}, [%4];"
                 : "=r"(r0), "=r"(r1), "=r"(r2), "=r"(r3) : "r"(addr));
}
__device__ __forceinline__ void mma16816(float* c, const u32* a, const u32* b) {
    asm volatile("mma.sync.aligned.m16n8k16.row.col.f32.f16.f16.f32 "
                 "{%0,%1,%2,%3}, {%4,%5,%6,%7}, {%8,%9}, {%0,%1,%2,%3};"
                 : "+f"(c[0]), "+f"(c[1]), "+f"(c[2]), "+f"(c[3])
                 : "r"(a[0]), "r"(a[1]), "r"(a[2]), "r"(a[3]), "r"(b[0]), "r"(b[1]));
}

__device__ __forceinline__ u32 swz128(u32 off) { return off ^ ((off >> 3) & 0x70); }

// ---------------- fused prep kernel ------------------------------------------
// blocks [0, 4096): W rows -> fp16 + d = bias - c_e.W_row  (1 warp per row)
// blocks [4096, 6144): x -> fp16
__global__ void prep_kernel(const float* __restrict__ x,
                            const float* __restrict__ W,
                            const float* __restrict__ centers,
                            const float* __restrict__ bias) {
    int b = blockIdx.x;
    if (b < 4096) {
        int gw   = b * 8 + (threadIdx.x >> 5);
        int lane = threadIdx.x & 31;
        int e = gw >> 11;
        const float4* wr = (const float4*)(W + (size_t)gw * ND);
        const float4* cr = (const float4*)(centers + (size_t)e * ND);
        __half2* ph = (__half2*)(g_wh + (size_t)gw * ND);
        float s = 0.f;
#pragma unroll
        for (int i = 0; i < ND / 128; i++) {
            int idx = lane + 32 * i;
            float4 w4 = wr[idx];
            float4 c4 = cr[idx];
            s += w4.x * c4.x + w4.y * c4.y + w4.z * c4.z + w4.w * c4.w;
            ph[2 * idx]     = __half2(__float2half_rn(w4.x), __float2half_rn(w4.y));
            ph[2 * idx + 1] = __half2(__float2half_rn(w4.z), __float2half_rn(w4.w));
        }
#pragma unroll
        for (int o = 16; o; o >>= 1) s += __shfl_xor_sync(0xffffffffu, s, o);
        if (lane == 0) g_dcomb[gw] = bias[gw] - s;
    } else {
        int i = (b - 4096) * 256 + threadIdx.x;
        float4 v = ((const float4*)x)[i];
        __half2* ph = (__half2*)g_xh;
        ph[2 * i]     = __half2(__float2half_rn(v.x), __float2half_rn(v.y));
        ph[2 * i + 1] = __half2(__float2half_rn(v.z), __float2half_rn(v.w));
    }
}

// ---------------- main GEMM kernel -------------------------------------------
// grid (NH/128, NB/128) = (16, 32); 256 threads, 8 warps (2m x 4n of 64x32).
// 128 chunks = 16 experts x 8 k-chunks of 64; 2 chunks per barrier; fragment
// double-buffering pipelined across the intra-pair chunk boundary.

__device__ __forceinline__ void load_chunk(int gc, u32 dst, int mb, int hb, int tid) {
    int e = gc >> 3, kc = (gc & 7) * KC;
    int row = tid >> 3, c = tid & 7;
    u32 so = swz128((u32)(row * 128 + c * 16));
    const __half* pxh = g_xh + (size_t)(mb + row) * ND + kc + c * 8;
    const __half* pwh = g_wh + (size_t)(e * NH + hb + row) * ND + kc + c * 8;
#pragma unroll
    for (int i = 0; i < 4; i++) {
        u32 d = dst + so + (u32)i * 4096;          // +32 rows per step
        size_t eo = (size_t)(32 * i) * ND;
        cp16(d + 0 * TILE, pxh + eo);
        cp16(d + 1 * TILE, pwh + eo);
    }
}

__device__ __forceinline__ void load_frags(int ks, u32 Ah, u32 Bh, int wm, int wn,
                                           int lane, u32 ah[4][4], u32 bh[4][2]) {
    u32 arel = swz128((u32)((lane & 15) * 128 + ks * 32 + (lane >> 4) * 16));
#pragma unroll
    for (int mt = 0; mt < 4; mt++) {
        u32 ao = (u32)((wm + mt * 16) * 128) + arel;
        ldsm4(ah[mt][0], ah[mt][1], ah[mt][2], ah[mt][3], Ah + ao);
    }
    u32 brel = swz128((u32)((lane & 7) * 128 + ks * 32 + ((lane >> 3) & 1) * 16));
#pragma unroll
    for (int pr = 0; pr < 2; pr++) {
        u32 bo = (u32)((wn + pr * 16 + ((lane >> 4) & 1) * 8) * 128) + brel;
        ldsm4(bh[pr * 2][0], bh[pr * 2][1], bh[pr * 2 + 1][0], bh[pr * 2 + 1][1], Bh + bo);
    }
}

__global__ void __launch_bounds__(256, 1)
gemm_kernel(float* __restrict__ out) {
    extern __shared__ char smem[];
    float* dsm = (float*)smem;                     // [16][128] combined bias
    u32 sb = smem_u32(smem) + OFF_STAGES;
    const int tid = threadIdx.x, wid = tid >> 5, lane = tid & 31;
    const int hb = blockIdx.x * 128, mb = blockIdx.y * 128;
    const int wm = (wid >> 2) * 64, wn = (wid & 3) * 32;

    // stage the per-expert combined bias slice for this CTA
#pragma unroll
    for (int i = tid; i < NE * 128; i += 256)
        dsm[i] = g_dcomb[(size_t)(i >> 7) * NH + hb + (i & 127)];

    // prologue: group G0 = chunks 0,1; G1 = chunks 2,3
    load_chunk(0, sb + 0 * STAGE, mb, hb, tid);
    load_chunk(1, sb + 1 * STAGE, mb, hb, tid); cp_commit();
    load_chunk(2, sb + 2 * STAGE, mb, hb, tid);
    load_chunk(3, sb + 3 * STAGE, mb, hb, tid); cp_commit();

    float acc[4][4][4], oacc[4][4][4];
#pragma unroll
    for (int a = 0; a < 4; a++)
#pragma unroll
        for (int b = 0; b < 4; b++)
#pragma unroll
            for (int c = 0; c < 4; c++) { acc[a][b][c] = 0.f; oacc[a][b][c] = 0.f; }

    u32 ah[2][4][4], bh[2][4][2];

    for (int j = 0; j < 64; j++) {     // iteration = chunk pair (2j, 2j+1)
        int c0 = 2 * j;
        // group j covers this pair; wait all but the newest 1 group -> G_j done
        cp_wait1();
        __syncthreads();

        u32 s0 = sb + (u32)(c0 % NSTAGE) * STAGE;
        u32 s1 = sb + (u32)((c0 + 1) % NSTAGE) * STAGE;
        u32 A0 = s0, B0 = s0 + TILE, A1 = s1, B1 = s1 + TILE;

        // kick off first fragment load, then overlap the global prefetch with it
        load_frags(0, A0, B0, wm, wn, lane, ah[0], bh[0]);

        if (c0 + 4 < 128) {            // group j+2 = chunks 2j+4, 2j+5
            load_chunk(c0 + 4, sb + (u32)((c0 + 4) % NSTAGE) * STAGE, mb, hb, tid);
            load_chunk(c0 + 5, sb + (u32)((c0 + 5) % NSTAGE) * STAGE, mb, hb, tid);
        }
        cp_commit();

        // chunk c0: ks 0..3; at ks3 preload chunk c1's ks0 (same barrier scope)
#pragma unroll
        for (int ks = 0; ks < 4; ks++) {
            int cur = ks & 1;
            if (ks < 3) load_frags(ks + 1, A0, B0, wm, wn, lane, ah[cur ^ 1], bh[cur ^ 1]);
            else        load_frags(0,      A1, B1, wm, wn, lane, ah[cur ^ 1], bh[cur ^ 1]);
#pragma unroll
            for (int mt = 0; mt < 4; mt++)
#pragma unroll
                for (int nt = 0; nt < 4; nt++)
                    mma16816(acc[mt][nt], ah[cur][mt], bh[cur][nt]);
        }

        // chunk c1: frags continue parity (ks0 sits in buffer 0)
#pragma unroll
        for (int ks = 0; ks < 4; ks++) {
            int cur = ks & 1;
            if (ks < 3) load_frags(ks + 1, A1, B1, wm, wn, lane, ah[cur ^ 1], bh[cur ^ 1]);
#pragma unroll
            for (int mt = 0; mt < 4; mt++)
#pragma unroll
                for (int nt = 0; nt < 4; nt++)
                    mma16816(acc[mt][nt], ah[cur][mt], bh[cur][nt]);
        }

        if ((j & 3) == 3) {            // finished expert e = j>>2: relu + accumulate
            int e = j >> 2;
            const float2* dp = (const float2*)(dsm + e * 128 + wn);
#pragma unroll
            for (int nt = 0; nt < 4; nt++) {
                float2 d2 = dp[nt * 4 + (lane & 3)];
#pragma unroll
                for (int mt = 0; mt < 4; mt++) {
                    oacc[mt][nt][0] += fmaxf(acc[mt][nt][0] + d2.x, 0.f);
                    oacc[mt][nt][1] += fmaxf(acc[mt][nt][1] + d2.y, 0.f);
                    oacc[mt][nt][2] += fmaxf(acc[mt][nt][2] + d2.x, 0.f);
                    oacc[mt][nt][3] += fmaxf(acc[mt][nt][3] + d2.y, 0.f);
                    acc[mt][nt][0] = 0.f; acc[mt][nt][1] = 0.f;
                    acc[mt][nt][2] = 0.f; acc[mt][nt][3] = 0.f;
                }
            }
        }
    }

    // store: C fragment mapping — (row t/4 [+8], col 2*(t%4) [+1])
#pragma unroll
    for (int mt = 0; mt < 4; mt++)
#pragma unroll
        for (int nt = 0; nt < 4; nt++) {
            int r0 = mb + wm + mt * 16 + (lane >> 2);
            int cc = hb + wn + nt * 8 + 2 * (lane & 3);
            *(float2*)(out + (size_t)r0 * NH + cc) =
                make_float2(oacc[mt][nt][0], oacc[mt][nt][1]);
            *(float2*)(out + (size_t)(r0 + 8) * NH + cc) =
                make_float2(oacc[mt][nt][2], oacc[mt][nt][3]);
        }
}

// ---------------- launch -----------------------------------------------------
extern "C" void kernel_launch(void* const* d_in, const int* in_sizes, int n_in,
                              void* d_out, int out_size) {
    const float* x       = (const float*)d_in[0];  // [B, D]
    const float* centers = (const float*)d_in[1];  // [E, D]
    const float* W       = (const float*)d_in[2];  // [E, H, D]
    const float* bias    = (const float*)d_in[3];  // [E, H]
    float* out = (float*)d_out;                    // [B, H]

    cudaFuncSetAttribute(gemm_kernel, cudaFuncAttributeMaxDynamicSharedMemorySize, SMEM_TOTAL);

    prep_kernel<<<4096 + 2048, 256>>>(x, W, centers, bias);

    dim3 grid(NH / 128, NB / 128);   // (16, 32)
    gemm_kernel<<<grid, 256, SMEM_TOTAL>>>(out);
}